// round 7
// baseline (speedup 1.0000x reference)
#include <cuda_runtime.h>
#include <cuda_bf16.h>
#include <cstdint>

#define BM 128
#define BN 64
#define KC 32
#define RSB 80                        // smem row stride bytes (32 bf16 + 16B pad)
#define ABYTES (BM * RSB)             // 10240
#define BBYTES (BN * RSB)             // 5120
#define SBYTES (ABYTES + BBYTES)      // 15360
#define STAGES 3
#define SMEM_DYN (STAGES * SBYTES)    // 46080
#define NIT 48                        // 3 segments x 16 kc-blocks (K' = 1536)
#define NTHR 128

// ---------------- split-precision operand storage (bf16 hi/lo) ----------------
__device__ __align__(16) __nv_bfloat16 g_x1h[2048 * 512];
__device__ __align__(16) __nv_bfloat16 g_x1l[2048 * 512];
__device__ __align__(16) __nv_bfloat16 g_x2h[2048 * 512];
__device__ __align__(16) __nv_bfloat16 g_x2l[2048 * 512];
__device__ __align__(16) __nv_bfloat16 g_wh[64ull * 512 * 512];   // [k][q][p]
__device__ __align__(16) __nv_bfloat16 g_wl[64ull * 512 * 512];
__device__ __align__(16) __nv_bfloat16 g_tmph[2048ull * 32768];   // [bi][k*512+q]
__device__ __align__(16) __nv_bfloat16 g_tmpl[2048ull * 32768];

// ---------------- asm helpers ----------------
static __device__ __forceinline__ uint32_t s2u(const void* p) {
    uint32_t a;
    asm("{ .reg .u64 t; cvta.to.shared.u64 t, %1; cvt.u32.u64 %0, t; }" : "=r"(a) : "l"(p));
    return a;
}
#define CP16(dst, src) \
    asm volatile("cp.async.cg.shared.global [%0], [%1], 16;" :: "r"(dst), "l"(src) : "memory")
#define CP_COMMIT() asm volatile("cp.async.commit_group;" ::: "memory")
#define CP_WAIT()   asm volatile("cp.async.wait_group 1;" ::: "memory")
#define LDSM4(r0, r1, r2, r3, addr) \
    asm volatile("ldmatrix.sync.aligned.m8n8.x4.shared.b16 {%0,%1,%2,%3}, [%4];" \
                 : "=r"(r0), "=r"(r1), "=r"(r2), "=r"(r3) : "r"(addr))
#define MMA16816(d, a, b0, b1) \
    asm volatile("mma.sync.aligned.m16n8k16.row.col.f32.bf16.bf16.f32 " \
                 "{%0,%1,%2,%3}, {%4,%5,%6,%7}, {%8,%9}, {%0,%1,%2,%3};" \
                 : "+f"((d)[0]), "+f"((d)[1]), "+f"((d)[2]), "+f"((d)[3]) \
                 : "r"((a)[0]), "r"((a)[1]), "r"((a)[2]), "r"((a)[3]), "r"(b0), "r"(b1))

// GEMM core: 128-thread CTA, tile 128x64, warp tile 64x32 (2x2 warps),
// 3-stage cp.async pipeline, one small (4-warp) barrier per iteration.
#define GEMM_CORE(SEGA0, SEGA2, SEGB0, SEGB1)                                        \
    {                                                                                \
        _issue(0, SEGA0, SEGB0);                                                     \
        _issue(1, SEGA0, SEGB0);                                                     \
        _Pragma("unroll 1")                                                          \
        for (int it = 0; it < NIT; it++) {                                           \
            CP_WAIT();                                                               \
            __syncthreads();                                                         \
            int nx = it + 2;                                                         \
            if (nx < NIT) {                                                          \
                int seg = nx >> 4;                                                   \
                const __nv_bfloat16* pa = (seg == 2) ? SEGA2 : SEGA0;                \
                const __nv_bfloat16* pb = (seg == 1) ? SEGB1 : SEGB0;                \
                _issue(nx, pa, pb);                                                  \
            } else {                                                                 \
                CP_COMMIT();                                                         \
            }                                                                        \
            uint32_t sb = sbase + (it % STAGES) * SBYTES;                            \
            uint32_t aBase = sb + (wm + lrow) * RSB + lh * 16;                       \
            uint32_t bBase = sb + ABYTES + (wn + lrow) * RSB + lh * 16;              \
            _Pragma("unroll")                                                        \
            for (int kk = 0; kk < 2; kk++) {                                         \
                uint32_t af[4][4], br[2][4];                                         \
                _Pragma("unroll")                                                    \
                for (int mi = 0; mi < 4; mi++)                                       \
                    LDSM4(af[mi][0], af[mi][1], af[mi][2], af[mi][3],                \
                          aBase + mi * 16 * RSB + kk * 32);                          \
                _Pragma("unroll")                                                    \
                for (int nb = 0; nb < 2; nb++)                                       \
                    LDSM4(br[nb][0], br[nb][1], br[nb][2], br[nb][3],                \
                          bBase + nb * 16 * RSB + kk * 32);                          \
                _Pragma("unroll")                                                    \
                for (int mi = 0; mi < 4; mi++)                                       \
                    _Pragma("unroll")                                                \
                    for (int ni = 0; ni < 4; ni++)                                   \
                        MMA16816(acc[mi][ni], af[mi],                                \
                                 br[ni >> 1][ni & 1], br[ni >> 1][(ni & 1) + 2]);    \
            }                                                                        \
        }                                                                            \
    }

// ---------------- preprocessing ----------------
__global__ void __launch_bounds__(256) split_x_kernel(const float* __restrict__ x1,
                                                      const float* __restrict__ x2) {
    int i = blockIdx.x * 256 + threadIdx.x;
    const float* x = blockIdx.y ? x2 : x1;
    __nv_bfloat16* h  = blockIdx.y ? g_x2h : g_x1h;
    __nv_bfloat16* lo = blockIdx.y ? g_x2l : g_x1l;
    float v = x[i];
    __nv_bfloat16 hb = __float2bfloat16_rn(v);
    h[i] = hb;
    lo[i] = __float2bfloat16_rn(v - __bfloat162float(hb));
}

// W[k][p][q] -> g_wh/g_wl[k][q][p]
__global__ void __launch_bounds__(256) splitW_kernel(const float* __restrict__ w) {
    __shared__ float tile[32][33];
    int k = blockIdx.z, p0 = blockIdx.y * 32, q0 = blockIdx.x * 32;
    int tx = threadIdx.x & 31, ty = threadIdx.x >> 5;
    const float* src = w + ((size_t)k * 512 + p0) * 512 + q0;
#pragma unroll
    for (int r = 0; r < 32; r += 8) tile[ty + r][tx] = src[(size_t)(ty + r) * 512 + tx];
    __syncthreads();
    size_t dof = ((size_t)k * 512 + q0) * 512 + p0;
#pragma unroll
    for (int r = 0; r < 32; r += 8) {
        float v = tile[tx][ty + r];
        __nv_bfloat16 hb = __float2bfloat16_rn(v);
        g_wh[dof + (size_t)(ty + r) * 512 + tx] = hb;
        g_wl[dof + (size_t)(ty + r) * 512 + tx] =
            __float2bfloat16_rn(v - __bfloat162float(hb));
    }
}

// ---------------- stage 1: tmp[bi, k*512+q] = sum_p x1[bi,p] W[k,p,q] ----------------
__global__ void __launch_bounds__(NTHR, 4) stage1_kernel() {
    extern __shared__ __align__(16) char sm[];
    uint32_t sbase = s2u(sm);
    int t = threadIdx.x, l = t & 31, w = t >> 5;
    int m0 = blockIdx.x * BM, n0 = blockIdx.y * BN;
    int wm = (w & 1) * 64, wn = (w >> 1) * 32;
    int lrow = l & 15, lh = l >> 4;

    // A: 128 rows x 4 chunks / 128 thr = 4 ; B: 64 x 4 / 128 = 2
    uint32_t aOff[4], aDst[4], bOff[2], bDst[2];
#pragma unroll
    for (int i = 0; i < 4; i++) {
        int o = t * 4 + i, r = o >> 2, c = o & 3;
        aOff[i] = (uint32_t)(m0 + r) * 512 + c * 8;
        aDst[i] = r * RSB + c * 16;
    }
#pragma unroll
    for (int i = 0; i < 2; i++) {
        int o = t * 2 + i, r = o >> 2, c = o & 3;
        int ng = n0 + r, kf = ng >> 9, q = ng & 511;
        bOff[i] = (uint32_t)(kf * 512 + q) * 512 + c * 8;
        bDst[i] = ABYTES + r * RSB + c * 16;
    }
    float acc[4][4][4];
#pragma unroll
    for (int a = 0; a < 4; a++)
#pragma unroll
        for (int b = 0; b < 4; b++)
#pragma unroll
            for (int c = 0; c < 4; c++) acc[a][b][c] = 0.f;

    auto _issue = [&](int it, const __nv_bfloat16* pa, const __nv_bfloat16* pb) {
        int kb = it & 15;
        uint32_t sb = sbase + (it % STAGES) * SBYTES;
#pragma unroll
        for (int i = 0; i < 4; i++) CP16(sb + aDst[i], pa + aOff[i] + kb * KC);
#pragma unroll
        for (int i = 0; i < 2; i++) CP16(sb + bDst[i], pb + bOff[i] + kb * KC);
        CP_COMMIT();
    };

    GEMM_CORE(g_x1h, g_x1l, g_wh, g_wl)

    // epilogue: split C into bf16 hi/lo -> g_tmph/g_tmpl
#pragma unroll
    for (int mi = 0; mi < 4; mi++) {
        int r0 = m0 + wm + mi * 16 + (l >> 2);
#pragma unroll
        for (int ni = 0; ni < 4; ni++) {
            int c = n0 + wn + ni * 8 + (l & 3) * 2;
#pragma unroll
            for (int hrow = 0; hrow < 2; hrow++) {
                size_t idx = (size_t)(r0 + hrow * 8) * 32768 + c;
                float v0 = acc[mi][ni][hrow * 2], v1 = acc[mi][ni][hrow * 2 + 1];
                __nv_bfloat162 hh, ll;
                hh.x = __float2bfloat16_rn(v0);
                hh.y = __float2bfloat16_rn(v1);
                ll.x = __float2bfloat16_rn(v0 - __bfloat162float(hh.x));
                ll.y = __float2bfloat16_rn(v1 - __bfloat162float(hh.y));
                *(__nv_bfloat162*)&g_tmph[idx] = hh;
                *(__nv_bfloat162*)&g_tmpl[idx] = ll;
            }
        }
    }
}

// ---------------- stage 2: out[b,i,j,k] = sum_q tmp[bi,k,q] x2[bj,q] + bias ----------
// Per CTA: M=128 j-rows, N=64 (all k of ONE i), K'=1536.
__global__ void __launch_bounds__(NTHR, 4) stage2_kernel(const float* __restrict__ bias,
                                                         float* __restrict__ out) {
    extern __shared__ __align__(16) char sm[];
    __shared__ float s_bias[64];
    uint32_t sbase = s2u(sm);
    int t = threadIdx.x, l = t & 31, w = t >> 5;
    int b = blockIdx.z, i = blockIdx.y;
    int j0 = blockIdx.x * BM;
    int wm = (w & 1) * 64, wn = (w >> 1) * 32;
    int lrow = l & 15, lh = l >> 4;
    if (t < 64) s_bias[t] = bias[t];

    uint32_t aOff[4], aDst[4], bOff[2], bDst[2];
#pragma unroll
    for (int ii = 0; ii < 4; ii++) {
        int o = t * 4 + ii, r = o >> 2, c = o & 3;
        aOff[ii] = (uint32_t)(b * 256 + j0 + r) * 512 + c * 8;
        aDst[ii] = r * RSB + c * 16;
    }
#pragma unroll
    for (int ii = 0; ii < 2; ii++) {
        int o = t * 2 + ii, r = o >> 2, c = o & 3;   // r = k row 0..63
        bOff[ii] = (uint32_t)(b * 256 + i) * 32768 + r * 512 + c * 8;
        bDst[ii] = ABYTES + r * RSB + c * 16;
    }
    float acc[4][4][4];
#pragma unroll
    for (int a = 0; a < 4; a++)
#pragma unroll
        for (int bb = 0; bb < 4; bb++)
#pragma unroll
            for (int c = 0; c < 4; c++) acc[a][bb][c] = 0.f;

    auto _issue = [&](int it, const __nv_bfloat16* pa, const __nv_bfloat16* pb) {
        int kb = it & 15;
        uint32_t sb = sbase + (it % STAGES) * SBYTES;
#pragma unroll
        for (int ii = 0; ii < 4; ii++) CP16(sb + aDst[ii], pa + aOff[ii] + kb * KC);
#pragma unroll
        for (int ii = 0; ii < 2; ii++) CP16(sb + bDst[ii], pb + bOff[ii] + kb * KC);
        CP_COMMIT();
    };

    GEMM_CORE(g_x2h, g_x2l, g_tmph, g_tmpl)

    // epilogue: add bias, write fp32 out[b, i, j, k]
#pragma unroll
    for (int mi = 0; mi < 4; mi++) {
        int j = j0 + wm + mi * 16 + (l >> 2);
#pragma unroll
        for (int ni = 0; ni < 4; ni++) {
            int k = wn + ni * 8 + (l & 3) * 2;
            float bk0 = s_bias[k], bk1 = s_bias[k + 1];
#pragma unroll
            for (int hrow = 0; hrow < 2; hrow++) {
                size_t idx = ((size_t)(b * 256 + i) * 256 + j + hrow * 8) * 64 + k;
                float2 v = make_float2(acc[mi][ni][hrow * 2] + bk0,
                                       acc[mi][ni][hrow * 2 + 1] + bk1);
                *(float2*)&out[idx] = v;
            }
        }
    }
}

// ---------------- host ----------------
extern "C" void kernel_launch(void* const* d_in, const int* in_sizes, int n_in,
                              void* d_out, int out_size)
{
    const float* x1   = (const float*)d_in[0];
    const float* x2   = (const float*)d_in[1];
    const float* w    = (const float*)d_in[2];
    const float* bias = (const float*)d_in[3];
    float* out        = (float*)d_out;

    cudaFuncSetAttribute(stage1_kernel, cudaFuncAttributeMaxDynamicSharedMemorySize, SMEM_DYN);
    cudaFuncSetAttribute(stage2_kernel, cudaFuncAttributeMaxDynamicSharedMemorySize, SMEM_DYN);

    split_x_kernel<<<dim3(4096, 2), 256>>>(x1, x2);
    splitW_kernel<<<dim3(16, 16, 64), 256>>>(w);

    stage1_kernel<<<dim3(16, 512), NTHR, SMEM_DYN>>>();
    stage2_kernel<<<dim3(2, 256, 8), NTHR, SMEM_DYN>>>(bias, out);
}

// round 8
// speedup vs baseline: 2.1131x; 2.1131x over previous
#include <cuda_runtime.h>
#include <cuda_fp16.h>
#include <cstdint>

#define BM 128
#define BN 128
#define KC 32
#define RSB 80                        // smem row stride bytes (32 f16 + 16B pad)
#define TBYTES (BM * RSB)             // 10240 per tile
#define SBYTES (3 * TBYTES)           // 3 tiles per stage (2 split ops + 1 shared)
#define STAGES 3
#define SMEM_DYN (STAGES * SBYTES)    // 92160
#define NIT 16                        // 16 x KC=32 covers K=512; 2 MMA passes per iter

// ---------------- fp16 split-precision operand storage ----------------
__device__ __align__(16) __half g_x1h[2048 * 512];
__device__ __align__(16) __half g_x1l[2048 * 512];
__device__ __align__(16) __half g_x2h[2048 * 512];
__device__ __align__(16) __half g_wh[64ull * 512 * 512];   // [k][q][p] transposed
__device__ __align__(16) __half g_th[2048ull * 32768];     // tmp hi [bi][k*512+q]
__device__ __align__(16) __half g_tl[2048ull * 32768];     // tmp lo

// ---------------- asm helpers ----------------
static __device__ __forceinline__ uint32_t s2u(const void* p) {
    uint32_t a;
    asm("{ .reg .u64 t; cvta.to.shared.u64 t, %1; cvt.u32.u64 %0, t; }" : "=r"(a) : "l"(p));
    return a;
}
#define CP16(dst, src) \
    asm volatile("cp.async.cg.shared.global [%0], [%1], 16;" :: "r"(dst), "l"(src) : "memory")
#define CP_COMMIT() asm volatile("cp.async.commit_group;" ::: "memory")
#define CP_WAIT()   asm volatile("cp.async.wait_group 1;" ::: "memory")
#define LDSM4(r0, r1, r2, r3, addr) \
    asm volatile("ldmatrix.sync.aligned.m8n8.x4.shared.b16 {%0,%1,%2,%3}, [%4];" \
                 : "=r"(r0), "=r"(r1), "=r"(r2), "=r"(r3) : "r"(addr))
#define MMA16816(d, a, b0, b1) \
    asm volatile("mma.sync.aligned.m16n8k16.row.col.f32.f16.f16.f32 " \
                 "{%0,%1,%2,%3}, {%4,%5,%6,%7}, {%8,%9}, {%0,%1,%2,%3};" \
                 : "+f"((d)[0]), "+f"((d)[1]), "+f"((d)[2]), "+f"((d)[3]) \
                 : "r"((a)[0]), "r"((a)[1]), "r"((a)[2]), "r"((a)[3]), "r"(b0), "r"(b1))

// Core: per iteration, smem holds tiles T0, T1 (split operand pair) and T2
// (shared operand). Warp does, per kk half: LDSM shared frags once, then two
// 16-MMA passes (T0 x T2, T1 x T2) into the SAME accumulators.
// OP0/OP1 = the two M-side tiles? No: A-side = M rows. Which side is split
// differs per stage; both stages arrange: A-tiles = {op0, op1} at smem offs
// 0 and TBYTES, B-tile (shared n-side frags)... see per-stage comments.
#define GEMM_CORE()                                                                  \
    {                                                                                \
        _issue(0);                                                                   \
        _issue(1);                                                                   \
        _Pragma("unroll 1")                                                          \
        for (int it = 0; it < NIT; it++) {                                           \
            CP_WAIT();                                                               \
            __syncthreads();                                                         \
            if (it + 2 < NIT) _issue(it + 2); else CP_COMMIT();                      \
            uint32_t sb = sbase + (it % STAGES) * SBYTES;                            \
            uint32_t a0Base = sb + (wm + lrow) * RSB + lh * 16;                      \
            uint32_t a1Base = a0Base + TBYTES;                                       \
            uint32_t bBase  = sb + 2 * TBYTES + (wn + lrow) * RSB + lh * 16;         \
            _Pragma("unroll")                                                        \
            for (int kk = 0; kk < 2; kk++) {                                         \
                uint32_t br[2][4];                                                   \
                _Pragma("unroll")                                                    \
                for (int nb = 0; nb < 2; nb++)                                       \
                    LDSM4(br[nb][0], br[nb][1], br[nb][2], br[nb][3],                \
                          bBase + nb * 16 * RSB + kk * 32);                          \
                {                                                                    \
                    uint32_t af[4][4];                                               \
                    _Pragma("unroll")                                                \
                    for (int mi = 0; mi < 4; mi++)                                   \
                        LDSM4(af[mi][0], af[mi][1], af[mi][2], af[mi][3],            \
                              a0Base + mi * 16 * RSB + kk * 32);                     \
                    _Pragma("unroll")                                                \
                    for (int mi = 0; mi < 4; mi++)                                   \
                        _Pragma("unroll")                                            \
                        for (int ni = 0; ni < 4; ni++)                               \
                            MMA16816(acc[mi][ni], af[mi],                            \
                                     br[ni >> 1][ni & 1], br[ni >> 1][(ni & 1) + 2]);\
                }                                                                    \
                {                                                                    \
                    uint32_t af[4][4];                                               \
                    _Pragma("unroll")                                                \
                    for (int mi = 0; mi < 4; mi++)                                   \
                        LDSM4(af[mi][0], af[mi][1], af[mi][2], af[mi][3],            \
                              a1Base + mi * 16 * RSB + kk * 32);                     \
                    _Pragma("unroll")                                                \
                    for (int mi = 0; mi < 4; mi++)                                   \
                        _Pragma("unroll")                                            \
                        for (int ni = 0; ni < 4; ni++)                               \
                            MMA16816(acc[mi][ni], af[mi],                            \
                                     br[ni >> 1][ni & 1], br[ni >> 1][(ni & 1) + 2]);\
                }                                                                    \
            }                                                                        \
        }                                                                            \
    }

// ---------------- preprocessing ----------------
// y=0: x1 -> (h, l).  y=1: x2 -> h only (x2 low is dropped by the scheme).
__global__ void __launch_bounds__(256) split_x_kernel(const float* __restrict__ x1,
                                                      const float* __restrict__ x2) {
    int i = blockIdx.x * 256 + threadIdx.x;
    if (blockIdx.y == 0) {
        float v = x1[i];
        __half h = __float2half_rn(v);
        g_x1h[i] = h;
        g_x1l[i] = __float2half_rn(v - __half2float(h));
    } else {
        g_x2h[i] = __float2half_rn(x2[i]);
    }
}

// W[k][p][q] -> g_wh[k][q][p] (transpose, fp16 hi only — W low is dropped)
__global__ void __launch_bounds__(256) splitW_kernel(const float* __restrict__ w) {
    __shared__ float tile[32][33];
    int k = blockIdx.z, p0 = blockIdx.y * 32, q0 = blockIdx.x * 32;
    int tx = threadIdx.x & 31, ty = threadIdx.x >> 5;
    const float* src = w + ((size_t)k * 512 + p0) * 512 + q0;
#pragma unroll
    for (int r = 0; r < 32; r += 8) tile[ty + r][tx] = src[(size_t)(ty + r) * 512 + tx];
    __syncthreads();
    size_t dof = ((size_t)k * 512 + q0) * 512 + p0;
#pragma unroll
    for (int r = 0; r < 32; r += 8)
        g_wh[dof + (size_t)(ty + r) * 512 + tx] = __float2half_rn(tile[tx][ty + r]);
}

// ---------------- stage 1: tmp[bi, k*512+q] = sum_p (x1h+x1l)[bi,p] Wh[k,p,q] -------
// A ops = {x1h, x1l} (M side, split), B = Wh (N side, shared).
__global__ void __launch_bounds__(256, 2) stage1_kernel() {
    extern __shared__ __align__(16) char sm[];
    uint32_t sbase = s2u(sm);
    int t = threadIdx.x, l = t & 31, w = t >> 5;
    int m0 = blockIdx.x * BM, n0 = blockIdx.y * BN;
    int wm = (w >> 2) * 64, wn = (w & 3) * 32;
    int lrow = l & 15, lh = l >> 4;

    uint32_t aOff[2], aDst[2], bOff[2], bDst[2];
#pragma unroll
    for (int i = 0; i < 2; i++) {
        int o = t * 2 + i, r = o >> 2, c = o & 3;
        aOff[i] = (uint32_t)(m0 + r) * 512 + c * 8;
        aDst[i] = r * RSB + c * 16;
        int ng = n0 + r, kf = ng >> 9, q = ng & 511;
        bOff[i] = (uint32_t)(kf * 512 + q) * 512 + c * 8;
        bDst[i] = 2 * TBYTES + r * RSB + c * 16;
    }
    float acc[4][4][4];
#pragma unroll
    for (int a = 0; a < 4; a++)
#pragma unroll
        for (int b = 0; b < 4; b++)
#pragma unroll
            for (int c = 0; c < 4; c++) acc[a][b][c] = 0.f;

    auto _issue = [&](int it) {
        uint32_t ko = it * KC;
        uint32_t sb = sbase + (it % STAGES) * SBYTES;
#pragma unroll
        for (int i = 0; i < 2; i++) {
            CP16(sb + aDst[i], g_x1h + aOff[i] + ko);
            CP16(sb + TBYTES + aDst[i], g_x1l + aOff[i] + ko);
            CP16(sb + bDst[i], g_wh + bOff[i] + ko);
        }
        CP_COMMIT();
    };

    GEMM_CORE()

    // epilogue: split C into fp16 hi/lo -> g_th/g_tl
#pragma unroll
    for (int mi = 0; mi < 4; mi++) {
        int r0 = m0 + wm + mi * 16 + (l >> 2);
#pragma unroll
        for (int ni = 0; ni < 4; ni++) {
            int c = n0 + wn + ni * 8 + (l & 3) * 2;
#pragma unroll
            for (int hrow = 0; hrow < 2; hrow++) {
                size_t idx = (size_t)(r0 + hrow * 8) * 32768 + c;
                float v0 = acc[mi][ni][hrow * 2], v1 = acc[mi][ni][hrow * 2 + 1];
                __half2 hh, ll;
                hh.x = __float2half_rn(v0);
                hh.y = __float2half_rn(v1);
                ll.x = __float2half_rn(v0 - __half2float(hh.x));
                ll.y = __float2half_rn(v1 - __half2float(hh.y));
                *(__half2*)&g_th[idx] = hh;
                *(__half2*)&g_tl[idx] = ll;
            }
        }
    }
}

// ---------------- stage 2: out[b,i,j,k] = sum_q x2h[bj,q] (th+tl)[bi,k,q] + bias ----
// A ops = {th-rows?? no}: here A side (M=j rows) = x2h is the SHARED operand;
// the split pair is on the B side (th, tl). We place the split pair in slots
// 0/1 and the shared x2h in slot 2 of smem, and swap roles in the core by
// mapping: a0/a1 tiles = x2h twice? Cheaper: keep core as-is with
// a0 = x2h, a1 = x2h (same data)?? wasteful. Instead: A = x2h once; B pair.
// We reuse GEMM_CORE by putting x2h in BOTH a0 and... no — write the mirror:
// slot0 = x2h (A), slot1 = th (B0), slot2 = tl (B1); per kk: LDSM A once,
// two B-frag sets, two MMA passes into same acc.
__global__ void __launch_bounds__(256, 2) stage2_kernel(const float* __restrict__ bias,
                                                        float* __restrict__ out) {
    extern __shared__ __align__(16) char sm[];
    __shared__ float s_bias[64];
    uint32_t sbase = s2u(sm);
    int t = threadIdx.x, l = t & 31, w = t >> 5;
    int bz = blockIdx.z;
    int b = bz >> 6, i0 = (bz & 63) * 4;
    int j0 = blockIdx.x * BM, n0 = blockIdx.y * BN;
    int wm = (w >> 2) * 64, wn = (w & 3) * 32;
    int lrow = l & 15, lh = l >> 4;
    if (t < 64) s_bias[t] = bias[t];

    uint32_t aOff[2], aDst[2], bOff[2], bDst[2];
#pragma unroll
    for (int i = 0; i < 2; i++) {
        int o = t * 2 + i, r = o >> 2, c = o & 3;
        aOff[i] = (uint32_t)(b * 256 + j0 + r) * 512 + c * 8;
        aDst[i] = r * RSB + c * 16;
        int ng = n0 + r, il = ng >> 6, k = ng & 63;
        bOff[i] = (uint32_t)(b * 256 + i0 + il) * 32768 + k * 512 + c * 8;
        bDst[i] = TBYTES + r * RSB + c * 16;
    }
    float acc[4][4][4];
#pragma unroll
    for (int a = 0; a < 4; a++)
#pragma unroll
        for (int bb = 0; bb < 4; bb++)
#pragma unroll
            for (int c = 0; c < 4; c++) acc[a][bb][c] = 0.f;

    auto _issue = [&](int it) {
        uint32_t ko = it * KC;
        uint32_t sb = sbase + (it % STAGES) * SBYTES;
#pragma unroll
        for (int i = 0; i < 2; i++) {
            CP16(sb + aDst[i], g_x2h + aOff[i] + ko);
            CP16(sb + bDst[i], g_th + bOff[i] + ko);
            CP16(sb + TBYTES + bDst[i], g_tl + bOff[i] + ko);
        }
        CP_COMMIT();
    };

    // mirror of GEMM_CORE: shared A frags, split B pair
    _issue(0);
    _issue(1);
#pragma unroll 1
    for (int it = 0; it < NIT; it++) {
        CP_WAIT();
        __syncthreads();
        if (it + 2 < NIT) _issue(it + 2); else CP_COMMIT();
        uint32_t sb = sbase + (it % STAGES) * SBYTES;
        uint32_t aBase  = sb + (wm + lrow) * RSB + lh * 16;
        uint32_t b0Base = sb + TBYTES + (wn + lrow) * RSB + lh * 16;
        uint32_t b1Base = b0Base + TBYTES;
#pragma unroll
        for (int kk = 0; kk < 2; kk++) {
            uint32_t af[4][4];
#pragma unroll
            for (int mi = 0; mi < 4; mi++)
                LDSM4(af[mi][0], af[mi][1], af[mi][2], af[mi][3],
                      aBase + mi * 16 * RSB + kk * 32);
            {
                uint32_t br[2][4];
#pragma unroll
                for (int nb = 0; nb < 2; nb++)
                    LDSM4(br[nb][0], br[nb][1], br[nb][2], br[nb][3],
                          b0Base + nb * 16 * RSB + kk * 32);
#pragma unroll
                for (int mi = 0; mi < 4; mi++)
#pragma unroll
                    for (int ni = 0; ni < 4; ni++)
                        MMA16816(acc[mi][ni], af[mi],
                                 br[ni >> 1][ni & 1], br[ni >> 1][(ni & 1) + 2]);
            }
            {
                uint32_t br[2][4];
#pragma unroll
                for (int nb = 0; nb < 2; nb++)
                    LDSM4(br[nb][0], br[nb][1], br[nb][2], br[nb][3],
                          b1Base + nb * 16 * RSB + kk * 32);
#pragma unroll
                for (int mi = 0; mi < 4; mi++)
#pragma unroll
                    for (int ni = 0; ni < 4; ni++)
                        MMA16816(acc[mi][ni], af[mi],
                                 br[ni >> 1][ni & 1], br[ni >> 1][(ni & 1) + 2]);
            }
        }
    }

    // epilogue: add bias, write fp32 out[b, i0+il, j, k]
#pragma unroll
    for (int mi = 0; mi < 4; mi++) {
        int j = j0 + wm + mi * 16 + (l >> 2);
#pragma unroll
        for (int ni = 0; ni < 4; ni++) {
            int c = n0 + wn + ni * 8 + (l & 3) * 2;
            int il = c >> 6, k = c & 63;
            float bk0 = s_bias[k], bk1 = s_bias[k + 1];
#pragma unroll
            for (int hrow = 0; hrow < 2; hrow++) {
                size_t idx = ((size_t)(b * 256 + i0 + il) * 256 + j + hrow * 8) * 64 + k;
                float2 v = make_float2(acc[mi][ni][hrow * 2] + bk0,
                                       acc[mi][ni][hrow * 2 + 1] + bk1);
                *(float2*)&out[idx] = v;
            }
        }
    }
}

// ---------------- host ----------------
extern "C" void kernel_launch(void* const* d_in, const int* in_sizes, int n_in,
                              void* d_out, int out_size)
{
    const float* x1   = (const float*)d_in[0];
    const float* x2   = (const float*)d_in[1];
    const float* w    = (const float*)d_in[2];
    const float* bias = (const float*)d_in[3];
    float* out        = (float*)d_out;

    cudaFuncSetAttribute(stage1_kernel, cudaFuncAttributeMaxDynamicSharedMemorySize, SMEM_DYN);
    cudaFuncSetAttribute(stage2_kernel, cudaFuncAttributeMaxDynamicSharedMemorySize, SMEM_DYN);

    split_x_kernel<<<dim3(4096, 2), 256>>>(x1, x2);
    splitW_kernel<<<dim3(16, 16, 64), 256>>>(w);

    stage1_kernel<<<dim3(16, 256), 256, SMEM_DYN>>>();
    stage2_kernel<<<dim3(2, 2, 512), 256, SMEM_DYN>>>(bias, out);
}

// round 9
// speedup vs baseline: 3.6415x; 1.7233x over previous
#include <cuda_runtime.h>
#include <cuda_fp16.h>
#include <cstdint>

#define BM 128
#define BN 128
#define KC 32
#define RSB 80                        // smem row stride bytes (32 f16 + 16B pad)
#define TBYTES (BM * RSB)             // 10240 per tile
#define SBYTES (2 * TBYTES)           // A + B per stage = 20480
#define STAGES 3
#define SMEM_DYN (STAGES * SBYTES)    // 61440
#define NIT 16                        // 16 x KC=32 = K=512

// ---------------- fp16 operand storage ----------------
__device__ __align__(16) __half g_x1h[2048 * 512];
__device__ __align__(16) __half g_x2h[2048 * 512];
__device__ __align__(16) __half g_wh[64ull * 512 * 512];   // [k][q][p] transposed
__device__ __align__(16) __half g_th[2048ull * 32768];     // tmp [bi][k*512+q]

// ---------------- asm helpers ----------------
static __device__ __forceinline__ uint32_t s2u(const void* p) {
    uint32_t a;
    asm("{ .reg .u64 t; cvta.to.shared.u64 t, %1; cvt.u32.u64 %0, t; }" : "=r"(a) : "l"(p));
    return a;
}
#define CP16(dst, src) \
    asm volatile("cp.async.cg.shared.global [%0], [%1], 16;" :: "r"(dst), "l"(src) : "memory")
#define CP_COMMIT() asm volatile("cp.async.commit_group;" ::: "memory")
#define CP_WAIT()   asm volatile("cp.async.wait_group 1;" ::: "memory")
#define LDSM4(r0, r1, r2, r3, addr) \
    asm volatile("ldmatrix.sync.aligned.m8n8.x4.shared.b16 {%0,%1,%2,%3}, [%4];" \
                 : "=r"(r0), "=r"(r1), "=r"(r2), "=r"(r3) : "r"(addr))
#define MMA16816(d, a, b0, b1) \
    asm volatile("mma.sync.aligned.m16n8k16.row.col.f32.f16.f16.f32 " \
                 "{%0,%1,%2,%3}, {%4,%5,%6,%7}, {%8,%9}, {%0,%1,%2,%3};" \
                 : "+f"((d)[0]), "+f"((d)[1]), "+f"((d)[2]), "+f"((d)[3]) \
                 : "r"((a)[0]), "r"((a)[1]), "r"((a)[2]), "r"((a)[3]), "r"(b0), "r"(b1))

// GEMM core: 128x128 CTA tile, warp tile 64x32 (2Mx4N warps), KC=32,
// 3-stage cp.async pipeline, single fp16 MMA pass per k-chunk.
#define GEMM_CORE()                                                                  \
    {                                                                                \
        _issue(0);                                                                   \
        _issue(1);                                                                   \
        _Pragma("unroll 1")                                                          \
        for (int it = 0; it < NIT; it++) {                                           \
            CP_WAIT();                                                               \
            __syncthreads();                                                         \
            if (it + 2 < NIT) _issue(it + 2); else CP_COMMIT();                      \
            uint32_t sb = sbase + (it % STAGES) * SBYTES;                            \
            uint32_t aBase = sb + (wm + lrow) * RSB + lh * 16;                       \
            uint32_t bBase = sb + TBYTES + (wn + lrow) * RSB + lh * 16;              \
            _Pragma("unroll")                                                        \
            for (int kk = 0; kk < 2; kk++) {                                         \
                uint32_t af[4][4], br[2][4];                                         \
                _Pragma("unroll")                                                    \
                for (int mi = 0; mi < 4; mi++)                                       \
                    LDSM4(af[mi][0], af[mi][1], af[mi][2], af[mi][3],                \
                          aBase + mi * 16 * RSB + kk * 32);                          \
                _Pragma("unroll")                                                    \
                for (int nb = 0; nb < 2; nb++)                                       \
                    LDSM4(br[nb][0], br[nb][1], br[nb][2], br[nb][3],                \
                          bBase + nb * 16 * RSB + kk * 32);                          \
                _Pragma("unroll")                                                    \
                for (int mi = 0; mi < 4; mi++)                                       \
                    _Pragma("unroll")                                                \
                    for (int ni = 0; ni < 4; ni++)                                   \
                        MMA16816(acc[mi][ni], af[mi],                                \
                                 br[ni >> 1][ni & 1], br[ni >> 1][(ni & 1) + 2]);    \
            }                                                                        \
        }                                                                            \
    }

// ---------------- preprocessing ----------------
__global__ void __launch_bounds__(256) cvt_x_kernel(const float* __restrict__ x1,
                                                    const float* __restrict__ x2) {
    int i = blockIdx.x * 256 + threadIdx.x;
    if (blockIdx.y == 0) g_x1h[i] = __float2half_rn(x1[i]);
    else                 g_x2h[i] = __float2half_rn(x2[i]);
}

// W[k][p][q] -> g_wh[k][q][p] (transpose + fp16)
__global__ void __launch_bounds__(256) cvtW_kernel(const float* __restrict__ w) {
    __shared__ float tile[32][33];
    int k = blockIdx.z, p0 = blockIdx.y * 32, q0 = blockIdx.x * 32;
    int tx = threadIdx.x & 31, ty = threadIdx.x >> 5;
    const float* src = w + ((size_t)k * 512 + p0) * 512 + q0;
#pragma unroll
    for (int r = 0; r < 32; r += 8) tile[ty + r][tx] = src[(size_t)(ty + r) * 512 + tx];
    __syncthreads();
    size_t dof = ((size_t)k * 512 + q0) * 512 + p0;
#pragma unroll
    for (int r = 0; r < 32; r += 8)
        g_wh[dof + (size_t)(ty + r) * 512 + tx] = __float2half_rn(tile[tx][ty + r]);
}

// ---------------- stage 1: tmp[bi, k*512+q] = sum_p x1h[bi,p] Wh[k,p,q] ----------------
__global__ void __launch_bounds__(256, 2) stage1_kernel() {
    extern __shared__ __align__(16) char sm[];
    uint32_t sbase = s2u(sm);
    int t = threadIdx.x, l = t & 31, w = t >> 5;
    int m0 = blockIdx.x * BM, n0 = blockIdx.y * BN;
    int wm = (w >> 2) * 64, wn = (w & 3) * 32;
    int lrow = l & 15, lh = l >> 4;

    uint32_t aOff[2], aDst[2], bOff[2], bDst[2];
#pragma unroll
    for (int i = 0; i < 2; i++) {
        int o = t * 2 + i, r = o >> 2, c = o & 3;
        aOff[i] = (uint32_t)(m0 + r) * 512 + c * 8;
        aDst[i] = r * RSB + c * 16;
        int ng = n0 + r, kf = ng >> 9, q = ng & 511;
        bOff[i] = (uint32_t)(kf * 512 + q) * 512 + c * 8;
        bDst[i] = TBYTES + r * RSB + c * 16;
    }
    float acc[4][4][4];
#pragma unroll
    for (int a = 0; a < 4; a++)
#pragma unroll
        for (int b = 0; b < 4; b++)
#pragma unroll
            for (int c = 0; c < 4; c++) acc[a][b][c] = 0.f;

    auto _issue = [&](int it) {
        uint32_t ko = it * KC;
        uint32_t sb = sbase + (it % STAGES) * SBYTES;
#pragma unroll
        for (int i = 0; i < 2; i++) {
            CP16(sb + aDst[i], g_x1h + aOff[i] + ko);
            CP16(sb + bDst[i], g_wh + bOff[i] + ko);
        }
        CP_COMMIT();
    };

    GEMM_CORE()

    // epilogue: fp16-convert C -> g_th
#pragma unroll
    for (int mi = 0; mi < 4; mi++) {
        int r0 = m0 + wm + mi * 16 + (l >> 2);
#pragma unroll
        for (int ni = 0; ni < 4; ni++) {
            int c = n0 + wn + ni * 8 + (l & 3) * 2;
#pragma unroll
            for (int hrow = 0; hrow < 2; hrow++) {
                size_t idx = (size_t)(r0 + hrow * 8) * 32768 + c;
                __half2 hh;
                hh.x = __float2half_rn(acc[mi][ni][hrow * 2]);
                hh.y = __float2half_rn(acc[mi][ni][hrow * 2 + 1]);
                *(__half2*)&g_th[idx] = hh;
            }
        }
    }
}

// ---------------- stage 2: out[b,i0+il,j,k] = sum_q x2h[bj,q] th[bi,k,q] + bias ------
__global__ void __launch_bounds__(256, 2) stage2_kernel(const float* __restrict__ bias,
                                                        float* __restrict__ out) {
    extern __shared__ __align__(16) char sm[];
    __shared__ float s_bias[64];
    uint32_t sbase = s2u(sm);
    int t = threadIdx.x, l = t & 31, w = t >> 5;
    int bz = blockIdx.z;
    int b = bz >> 6, i0 = (bz & 63) * 4;
    int j0 = blockIdx.x * BM, n0 = blockIdx.y * BN;
    int wm = (w >> 2) * 64, wn = (w & 3) * 32;
    int lrow = l & 15, lh = l >> 4;
    if (t < 64) s_bias[t] = bias[t];

    uint32_t aOff[2], aDst[2], bOff[2], bDst[2];
#pragma unroll
    for (int i = 0; i < 2; i++) {
        int o = t * 2 + i, r = o >> 2, c = o & 3;
        aOff[i] = (uint32_t)(b * 256 + j0 + r) * 512 + c * 8;
        aDst[i] = r * RSB + c * 16;
        int ng = n0 + r, il = ng >> 6, k = ng & 63;
        bOff[i] = (uint32_t)(b * 256 + i0 + il) * 32768 + k * 512 + c * 8;
        bDst[i] = TBYTES + r * RSB + c * 16;
    }
    float acc[4][4][4];
#pragma unroll
    for (int a = 0; a < 4; a++)
#pragma unroll
        for (int bb = 0; bb < 4; bb++)
#pragma unroll
            for (int c = 0; c < 4; c++) acc[a][bb][c] = 0.f;

    auto _issue = [&](int it) {
        uint32_t ko = it * KC;
        uint32_t sb = sbase + (it % STAGES) * SBYTES;
#pragma unroll
        for (int i = 0; i < 2; i++) {
            CP16(sb + aDst[i], g_x2h + aOff[i] + ko);
            CP16(sb + bDst[i], g_th + bOff[i] + ko);
        }
        CP_COMMIT();
    };

    GEMM_CORE()

    // epilogue: add bias, write fp32 out[b, i0+il, j, k]
#pragma unroll
    for (int mi = 0; mi < 4; mi++) {
        int j = j0 + wm + mi * 16 + (l >> 2);
#pragma unroll
        for (int ni = 0; ni < 4; ni++) {
            int c = n0 + wn + ni * 8 + (l & 3) * 2;
            int il = c >> 6, k = c & 63;
            float bk0 = s_bias[k], bk1 = s_bias[k + 1];
#pragma unroll
            for (int hrow = 0; hrow < 2; hrow++) {
                size_t idx = ((size_t)(b * 256 + i0 + il) * 256 + j + hrow * 8) * 64 + k;
                float2 v = make_float2(acc[mi][ni][hrow * 2] + bk0,
                                       acc[mi][ni][hrow * 2 + 1] + bk1);
                *(float2*)&out[idx] = v;
            }
        }
    }
}

// ---------------- host ----------------
extern "C" void kernel_launch(void* const* d_in, const int* in_sizes, int n_in,
                              void* d_out, int out_size)
{
    const float* x1   = (const float*)d_in[0];
    const float* x2   = (const float*)d_in[1];
    const float* w    = (const float*)d_in[2];
    const float* bias = (const float*)d_in[3];
    float* out        = (float*)d_out;

    cudaFuncSetAttribute(stage1_kernel, cudaFuncAttributeMaxDynamicSharedMemorySize, SMEM_DYN);
    cudaFuncSetAttribute(stage2_kernel, cudaFuncAttributeMaxDynamicSharedMemorySize, SMEM_DYN);

    cvt_x_kernel<<<dim3(4096, 2), 256>>>(x1, x2);
    cvtW_kernel<<<dim3(16, 16, 64), 256>>>(w);

    stage1_kernel<<<dim3(16, 256), 256, SMEM_DYN>>>();
    stage2_kernel<<<dim3(2, 2, 512), 256, SMEM_DYN>>>(bias, out);
}